// round 2
// baseline (speedup 1.0000x reference)
#include <cuda_runtime.h>
#include <cstdint>

#define BB 2048
#define TT 1024
#define NFEAT 10
#define NSEQ 9
#define HID 128
#define MT 128
#define NTILES ((BB * TT) / MT)

// shared memory layout (in floats)
#define LDK 132   // row stride of transposed W2 (n-major, k contiguous)
#define LDA 132   // row stride of h1 (m-major, k contiguous)
#define LDSEQ 12
#define LDRED 33
#define OFF_W2T 0
#define OFF_A (OFF_W2T + HID * LDK)           // 16896
#define OFF_RED (OFF_A + HID * LDA)           // +16896
#define OFF_SEQ (OFF_RED + MT * LDRED)        // +4224
#define OFF_W1 (OFF_SEQ + MT * LDSEQ)         // +1536
#define OFF_B1 (OFF_W1 + NSEQ * HID)          // +1152
#define OFF_B2 (OFF_B1 + HID)
#define OFF_W3 (OFF_B2 + HID)
#define SMEM_FLOATS (OFF_W3 + HID * 2)
#define SMEM_BYTES (SMEM_FLOATS * 4)

typedef unsigned long long u64;

__device__ __forceinline__ float tanh_fast(float x) {
    asm("tanh.approx.f32 %0, %0;" : "+f"(x));
    return x;
}
__device__ __forceinline__ u64 ffma2(u64 a, u64 b, u64 c) {
    u64 d;
    asm("fma.rn.f32x2 %0, %1, %2, %3;" : "=l"(d) : "l"(a), "l"(b), "l"(c));
    return d;
}
__device__ __forceinline__ void unpk(u64 v, float& lo, float& hi) {
    asm("mov.b64 {%0, %1}, %2;" : "=f"(lo), "=f"(hi) : "l"(v));
}

// ---------------------------------------------------------------------------
// Kernel 1: RK4 scan over T per batch row. Writes xG(t) (pre-update state)
// into d_out; the NN kernel later adds r(t) in place.
// ---------------------------------------------------------------------------
__global__ void rk4_kernel(const float* __restrict__ inp,
                           const float* __restrict__ x0,
                           float* __restrict__ out) {
    int b = blockIdx.x * blockDim.x + threadIdx.x;
    if (b >= BB) return;
    float2 x = ((const float2*)x0)[b];
    float xa = x.x, xb = x.y;
    const float* up = inp + (size_t)b * TT * NFEAT;
    float2* op = (float2*)out + (size_t)b * TT;
    const float RT = 0.1f;          // 1/TAU
    const float HD2 = 0.05f;        // DELTA/2
    const float H = 0.1f;           // DELTA
    const float H6 = 0.1f / 6.0f;   // DELTA/6

    for (int t0 = 0; t0 < TT; t0 += 8) {
        float u[8];
#pragma unroll
        for (int j = 0; j < 8; j++) u[j] = up[(t0 + j) * NFEAT];
#pragma unroll
        for (int j = 0; j < 8; j++) {
            op[t0 + j] = make_float2(xa, xb);
            float uu = u[j];
            float k1a = (uu - xa) * RT - xa;
            float k1b = xa - xb * RT;
            float x2a = fmaf(HD2, k1a, xa), x2b = fmaf(HD2, k1b, xb);
            float k2a = (uu - x2a) * RT - x2a;
            float k2b = x2a - x2b * RT;
            float x3a = fmaf(HD2, k2a, xa), x3b = fmaf(HD2, k2b, xb);
            float k3a = (uu - x3a) * RT - x3a;
            float k3b = x3a - x3b * RT;
            float x4a = fmaf(H, k3a, xa), x4b = fmaf(H, k3b, xb);
            float k4a = (uu - x4a) * RT - x4a;
            float k4b = x4a - x4b * RT;
            xa = fmaf(H6, k1a + 2.0f * (k2a + k3a) + k4a, xa);
            xb = fmaf(H6, k1b + 2.0f * (k2b + k3b) + k4b, xb);
        }
    }
}

// ---------------------------------------------------------------------------
// Kernel 2: persistent fused MLP, 256 threads, 1 block/SM, weights resident
// in SMEM. GEMM packs the k-dimension into f32x2 lanes: both operands are
// natural 64-bit SMEM loads (zero packing MOVs); each acc u64 carries
// even-k / odd-k partial sums, folded in the epilogue.
// ---------------------------------------------------------------------------
__global__ __launch_bounds__(256, 1) void nn_kernel(
    const float* __restrict__ inp, const float* __restrict__ gW1,
    const float* __restrict__ gb1, const float* __restrict__ gW2,
    const float* __restrict__ gb2, const float* __restrict__ gW3,
    float* __restrict__ out) {
    extern __shared__ float sm[];
    float* sW2T = sm + OFF_W2T;
    float* sA = sm + OFF_A;
    float* sRed = sm + OFF_RED;
    float* sSeq = sm + OFF_SEQ;
    float* sW1 = sm + OFF_W1;
    float* sB1 = sm + OFF_B1;
    float* sB2 = sm + OFF_B2;
    float* sW3 = sm + OFF_W3;
    int tid = threadIdx.x;

    // phase 0: load + transpose weights once (persistent residency)
    for (int i = tid; i < HID * HID; i += 256) {
        int k = i >> 7, n = i & 127;
        sW2T[n * LDK + k] = gW2[i];
    }
    for (int i = tid; i < NSEQ * HID; i += 256) sW1[i] = gW1[i];
    if (tid < HID) {
        sB1[tid] = gb1[tid];
        sB2[tid] = gb2[tid];
    }
    for (int i = tid; i < HID * 2; i += 256) sW3[i] = gW3[i];
    __syncthreads();

    const int tx = tid & 15, ty = tid >> 4;
    const int m0 = ty * 8;                 // 8 token rows per thread
    // 8 n-columns per thread: n_j = tx + 16*j  (conflict-free W2T reads)
    float w3a[8], w3b[8], b2r[8];
#pragma unroll
    for (int j = 0; j < 8; j++) {
        int n = tx + 16 * j;
        w3a[j] = sW3[n * 2];
        w3b[j] = sW3[n * 2 + 1];
        b2r[j] = sB2[n];
    }
    const int kk = tid >> 1, mh = (tid & 1) << 6;
    float w1r[NSEQ];
#pragma unroll
    for (int j = 0; j < NSEQ; j++) w1r[j] = sW1[j * HID + kk];
    const float b1k = sB1[kk];

    for (int tile = blockIdx.x; tile < NTILES; tile += gridDim.x) {
        const int tok0 = tile * MT;
        __syncthreads();  // protect smem reuse across tile iterations

        // load seq features (9 of 10) for this tile
        for (int i = tid; i < MT * NSEQ; i += 256) {
            int m = i / NSEQ, j = i - m * NSEQ;
            sSeq[m * LDSEQ + j] = __ldg(&inp[(size_t)(tok0 + m) * NFEAT + 1 + j]);
        }
        __syncthreads();

        // phase 1: h1[m][k] = tanh(seq[m]·W1[:,k] + b1[k]), stored m-major
        {
            const float* sq = sSeq + mh * LDSEQ;
            float* outcol = sA + mh * LDA + kk;
#pragma unroll 4
            for (int mm = 0; mm < 64; mm++) {
                const float* s = sq + mm * LDSEQ;
                float4 s0 = *(const float4*)(s);
                float4 s1 = *(const float4*)(s + 4);
                float s8 = s[8];
                float acc = b1k;
                acc = fmaf(s0.x, w1r[0], acc);
                acc = fmaf(s0.y, w1r[1], acc);
                acc = fmaf(s0.z, w1r[2], acc);
                acc = fmaf(s0.w, w1r[3], acc);
                acc = fmaf(s1.x, w1r[4], acc);
                acc = fmaf(s1.y, w1r[5], acc);
                acc = fmaf(s1.z, w1r[6], acc);
                acc = fmaf(s1.w, w1r[7], acc);
                acc = fmaf(s8, w1r[8], acc);
                outcol[mm * LDA] = tanh_fast(acc);
            }
        }
        __syncthreads();

        // phase 2: 128x128x128 GEMM, k-pairs packed in f32x2 lanes
        u64 acc[8][8];
#pragma unroll
        for (int i = 0; i < 8; i++)
#pragma unroll
            for (int j = 0; j < 8; j++) acc[i][j] = 0ull;
#pragma unroll 1
        for (int ks = 0; ks < HID; ks += 4) {
            ulonglong2 bv[8];
#pragma unroll
            for (int j = 0; j < 8; j++)
                bv[j] = *(const ulonglong2*)(sW2T + (tx + 16 * j) * LDK + ks);
#pragma unroll
            for (int i = 0; i < 8; i++) {
                ulonglong2 av = *(const ulonglong2*)(sA + (m0 + i) * LDA + ks);
#pragma unroll
                for (int j = 0; j < 8; j++) {
                    acc[i][j] = ffma2(av.x, bv[j].x, acc[i][j]);
                    acc[i][j] = ffma2(av.y, bv[j].y, acc[i][j]);
                }
            }
        }

        // epilogue: fold k-lanes, bias + tanh + W3 partials -> sRed
#pragma unroll
        for (int i = 0; i < 8; i++) {
            float s0 = 0.f, s1 = 0.f;
#pragma unroll
            for (int j = 0; j < 8; j++) {
                float lo, hi;
                unpk(acc[i][j], lo, hi);
                float h = tanh_fast(lo + hi + b2r[j]);
                s0 = fmaf(h, w3a[j], s0);
                s1 = fmaf(h, w3b[j], s1);
            }
            sRed[(m0 + i) * LDRED + tx] = s0;
            sRed[(m0 + i) * LDRED + 16 + tx] = s1;
        }
        __syncthreads();

        // reduce 16 partials and add to xG already in d_out
        {
            int m = tid >> 1, c = tid & 1;
            const float* rp = sRed + m * LDRED + c * 16;
            float a0 = rp[0] + rp[1], a1 = rp[2] + rp[3];
            float a2 = rp[4] + rp[5], a3 = rp[6] + rp[7];
            float a4 = rp[8] + rp[9], a5 = rp[10] + rp[11];
            float a6 = rp[12] + rp[13], a7 = rp[14] + rp[15];
            float s = ((a0 + a1) + (a2 + a3)) + ((a4 + a5) + (a6 + a7));
            size_t oidx = ((size_t)(tok0 + m)) * 2 + c;
            out[oidx] += s;
        }
    }
}

// ---------------------------------------------------------------------------
extern "C" void kernel_launch(void* const* d_in, const int* in_sizes, int n_in,
                              void* d_out, int out_size) {
    const float* inp = (const float*)d_in[0];
    const float* x0 = (const float*)d_in[1];
    const float* W1 = (const float*)d_in[2];
    const float* b1 = (const float*)d_in[3];
    const float* W2 = (const float*)d_in[4];
    const float* b2 = (const float*)d_in[5];
    const float* W3 = (const float*)d_in[6];
    float* out = (float*)d_out;

    cudaFuncSetAttribute(nn_kernel, cudaFuncAttributeMaxDynamicSharedMemorySize,
                         SMEM_BYTES);

    rk4_kernel<<<BB / 256, 256>>>(inp, x0, out);
    nn_kernel<<<148, 256, SMEM_BYTES>>>(inp, W1, b1, W2, b2, W3, out);
}

// round 3
// speedup vs baseline: 1.0106x; 1.0106x over previous
#include <cuda_runtime.h>
#include <cstdint>

#define BB 2048
#define TT 1024
#define NFEAT 10
#define NSEQ 9
#define HID 128
#define MT 128
#define NTILES ((BB * TT) / MT)
#define THREADS 512

// shared memory layout (in floats)
#define LDK 132   // row stride of transposed W2 (n-major, k contiguous)
#define LDA 132   // row stride of h1 (m-major, k contiguous)
#define LDSEQ 12
#define LDRED 33
#define OFF_W2T 0
#define OFF_A (OFF_W2T + HID * LDK)
#define OFF_RED (OFF_A + HID * LDA)
#define OFF_SEQ (OFF_RED + MT * LDRED)
#define OFF_W1 (OFF_SEQ + MT * LDSEQ)
#define OFF_B1 (OFF_W1 + NSEQ * HID)
#define OFF_B2 (OFF_B1 + HID)
#define OFF_W3 (OFF_B2 + HID)
#define SMEM_FLOATS (OFF_W3 + HID * 2)
#define SMEM_BYTES (SMEM_FLOATS * 4)

typedef unsigned long long u64;

__device__ __forceinline__ float tanh_fast(float x) {
    asm("tanh.approx.f32 %0, %0;" : "+f"(x));
    return x;
}
__device__ __forceinline__ u64 ffma2(u64 a, u64 b, u64 c) {
    u64 d;
    asm("fma.rn.f32x2 %0, %1, %2, %3;" : "=l"(d) : "l"(a), "l"(b), "l"(c));
    return d;
}
__device__ __forceinline__ void unpk(u64 v, float& lo, float& hi) {
    asm("mov.b64 {%0, %1}, %2;" : "=f"(lo), "=f"(hi) : "l"(v));
}

// ---------------------------------------------------------------------------
// Kernel 1: RK4 scan over T per batch row. Writes xG(t) (pre-update state)
// into d_out; the NN kernel later adds r(t) in place.
// ---------------------------------------------------------------------------
__global__ void rk4_kernel(const float* __restrict__ inp,
                           const float* __restrict__ x0,
                           float* __restrict__ out) {
    int b = blockIdx.x * blockDim.x + threadIdx.x;
    if (b >= BB) return;
    float2 x = ((const float2*)x0)[b];
    float xa = x.x, xb = x.y;
    const float* up = inp + (size_t)b * TT * NFEAT;
    float2* op = (float2*)out + (size_t)b * TT;
    const float RT = 0.1f;
    const float HD2 = 0.05f;
    const float H = 0.1f;
    const float H6 = 0.1f / 6.0f;

    for (int t0 = 0; t0 < TT; t0 += 8) {
        float u[8];
#pragma unroll
        for (int j = 0; j < 8; j++) u[j] = up[(t0 + j) * NFEAT];
#pragma unroll
        for (int j = 0; j < 8; j++) {
            op[t0 + j] = make_float2(xa, xb);
            float uu = u[j];
            float k1a = (uu - xa) * RT - xa;
            float k1b = xa - xb * RT;
            float x2a = fmaf(HD2, k1a, xa), x2b = fmaf(HD2, k1b, xb);
            float k2a = (uu - x2a) * RT - x2a;
            float k2b = x2a - x2b * RT;
            float x3a = fmaf(HD2, k2a, xa), x3b = fmaf(HD2, k2b, xb);
            float k3a = (uu - x3a) * RT - x3a;
            float k3b = x3a - x3b * RT;
            float x4a = fmaf(H, k3a, xa), x4b = fmaf(H, k3b, xb);
            float k4a = (uu - x4a) * RT - x4a;
            float k4b = x4a - x4b * RT;
            xa = fmaf(H6, k1a + 2.0f * (k2a + k3a) + k4a, xa);
            xb = fmaf(H6, k1b + 2.0f * (k2b + k3b) + k4b, xb);
        }
    }
}

// ---------------------------------------------------------------------------
// Kernel 2: persistent fused MLP, 512 threads (4 warps/SMSP), 1 block/SM.
// Weights resident in SMEM. GEMM packs k-pairs into f32x2 lanes so both
// FFMA2 operands come from natural 64-bit SMEM loads. Per-thread 4m x 8n.
// ---------------------------------------------------------------------------
__global__ __launch_bounds__(THREADS, 1) void nn_kernel(
    const float* __restrict__ inp, const float* __restrict__ gW1,
    const float* __restrict__ gb1, const float* __restrict__ gW2,
    const float* __restrict__ gb2, const float* __restrict__ gW3,
    float* __restrict__ out) {
    extern __shared__ float sm[];
    float* sW2T = sm + OFF_W2T;
    float* sA = sm + OFF_A;
    float* sRed = sm + OFF_RED;
    float* sSeq = sm + OFF_SEQ;
    float* sW1 = sm + OFF_W1;
    float* sB1 = sm + OFF_B1;
    float* sB2 = sm + OFF_B2;
    float* sW3 = sm + OFF_W3;
    const int tid = threadIdx.x;

    // phase 0: load + transpose weights once (persistent residency)
    for (int i = tid; i < HID * HID; i += THREADS) {
        int k = i >> 7, n = i & 127;
        sW2T[n * LDK + k] = gW2[i];
    }
    for (int i = tid; i < NSEQ * HID; i += THREADS) sW1[i] = gW1[i];
    if (tid < HID) {
        sB1[tid] = gb1[tid];
        sB2[tid] = gb2[tid];
    }
    for (int i = tid; i < HID * 2; i += THREADS) sW3[i] = gW3[i];
    __syncthreads();

    const int tx = tid & 15, ty = tid >> 4;   // ty in [0,32)
    const int m0 = ty * 4;                    // 4 token rows per thread
    const int kk = tid & 127, mq = (tid >> 7) * 32;  // phase-1 mapping

    for (int tile = blockIdx.x; tile < NTILES; tile += gridDim.x) {
        const int tok0 = tile * MT;
        __syncthreads();  // protect smem reuse across tile iterations

        // load seq features (9 of 10) for this tile
        for (int i = tid; i < MT * NSEQ; i += THREADS) {
            int m = i / NSEQ, j = i - m * NSEQ;
            sSeq[m * LDSEQ + j] = __ldg(&inp[(size_t)(tok0 + m) * NFEAT + 1 + j]);
        }
        __syncthreads();

        // phase 1: h1[m][k] = tanh(seq[m]·W1[:,k] + b1[k]), stored m-major.
        // Each thread: one k column (kk), 32 m rows (mq..mq+31).
        {
            float w1r[NSEQ];
#pragma unroll
            for (int j = 0; j < NSEQ; j++) w1r[j] = sW1[j * HID + kk];
            const float b1k = sB1[kk];
            const float* sq = sSeq + mq * LDSEQ;
            float* outcol = sA + mq * LDA + kk;
#pragma unroll 4
            for (int mm = 0; mm < 32; mm++) {
                const float* s = sq + mm * LDSEQ;
                float4 s0 = *(const float4*)(s);
                float4 s1 = *(const float4*)(s + 4);
                float s8 = s[8];
                float acc = b1k;
                acc = fmaf(s0.x, w1r[0], acc);
                acc = fmaf(s0.y, w1r[1], acc);
                acc = fmaf(s0.z, w1r[2], acc);
                acc = fmaf(s0.w, w1r[3], acc);
                acc = fmaf(s1.x, w1r[4], acc);
                acc = fmaf(s1.y, w1r[5], acc);
                acc = fmaf(s1.z, w1r[6], acc);
                acc = fmaf(s1.w, w1r[7], acc);
                acc = fmaf(s8, w1r[8], acc);
                outcol[mm * LDA] = tanh_fast(acc);
            }
        }
        __syncthreads();

        // phase 2: 128x128x128 GEMM, k-pairs packed in f32x2 lanes.
        // Per thread: rows m0..m0+3, cols tx+16j (j=0..7).
        u64 acc[4][8];
#pragma unroll
        for (int i = 0; i < 4; i++)
#pragma unroll
            for (int j = 0; j < 8; j++) acc[i][j] = 0ull;
#pragma unroll 1
        for (int ks = 0; ks < HID; ks += 4) {
            ulonglong2 bv[8];
#pragma unroll
            for (int j = 0; j < 8; j++)
                bv[j] = *(const ulonglong2*)(sW2T + (tx + 16 * j) * LDK + ks);
#pragma unroll
            for (int i = 0; i < 4; i++) {
                ulonglong2 av = *(const ulonglong2*)(sA + (m0 + i) * LDA + ks);
#pragma unroll
                for (int j = 0; j < 8; j++) {
                    acc[i][j] = ffma2(av.x, bv[j].x, acc[i][j]);
                    acc[i][j] = ffma2(av.y, bv[j].y, acc[i][j]);
                }
            }
        }

        // epilogue: fold k-lanes, bias + tanh + W3 partials -> sRed
        {
            float w3a[8], w3b[8], b2r[8];
#pragma unroll
            for (int j = 0; j < 8; j++) {
                int n = tx + 16 * j;
                w3a[j] = sW3[n * 2];
                w3b[j] = sW3[n * 2 + 1];
                b2r[j] = sB2[n];
            }
#pragma unroll
            for (int i = 0; i < 4; i++) {
                float s0 = 0.f, s1 = 0.f;
#pragma unroll
                for (int j = 0; j < 8; j++) {
                    float lo, hi;
                    unpk(acc[i][j], lo, hi);
                    float h = tanh_fast(lo + hi + b2r[j]);
                    s0 = fmaf(h, w3a[j], s0);
                    s1 = fmaf(h, w3b[j], s1);
                }
                sRed[(m0 + i) * LDRED + tx] = s0;
                sRed[(m0 + i) * LDRED + 16 + tx] = s1;
            }
        }
        __syncthreads();

        // reduce 16 partials and add to xG already in d_out
        if (tid < 256) {
            int m = tid >> 1, c = tid & 1;
            const float* rp = sRed + m * LDRED + c * 16;
            float a0 = rp[0] + rp[1], a1 = rp[2] + rp[3];
            float a2 = rp[4] + rp[5], a3 = rp[6] + rp[7];
            float a4 = rp[8] + rp[9], a5 = rp[10] + rp[11];
            float a6 = rp[12] + rp[13], a7 = rp[14] + rp[15];
            float s = ((a0 + a1) + (a2 + a3)) + ((a4 + a5) + (a6 + a7));
            size_t oidx = ((size_t)(tok0 + m)) * 2 + c;
            out[oidx] += s;
        }
    }
}

// ---------------------------------------------------------------------------
extern "C" void kernel_launch(void* const* d_in, const int* in_sizes, int n_in,
                              void* d_out, int out_size) {
    const float* inp = (const float*)d_in[0];
    const float* x0 = (const float*)d_in[1];
    const float* W1 = (const float*)d_in[2];
    const float* b1 = (const float*)d_in[3];
    const float* W2 = (const float*)d_in[4];
    const float* b2 = (const float*)d_in[5];
    const float* W3 = (const float*)d_in[6];
    float* out = (float*)d_out;

    cudaFuncSetAttribute(nn_kernel, cudaFuncAttributeMaxDynamicSharedMemorySize,
                         SMEM_BYTES);

    rk4_kernel<<<BB / 256, 256>>>(inp, x0, out);
    nn_kernel<<<148, THREADS, SMEM_BYTES>>>(inp, W1, b1, W2, b2, W3, out);
}

// round 5
// speedup vs baseline: 1.9664x; 1.9458x over previous
#include <cuda_runtime.h>
#include <cstdint>

#define BB 2048
#define TT 1024
#define NFEAT 10
#define NSEQ 9
#define HID 128
#define MT 128
#define NTILES ((BB * TT) / MT)
#define THREADS 512
#define GRID 148

// ---- shared memory layout (float / u32 units) ----
#define LDF 136                    // fragment array row stride (bank-free: 8t+g)
#define OFF_AT 0                   // h1 tf32, [k=128][m=128] stride 136
#define OFF_BT (OFF_AT + HID * LDF)    // W2 tf32, [k=128][n=128] stride 136
#define OFF_SEQ (OFF_BT + HID * LDF)   // 128 x 12 f32
#define OFF_W1 (OFF_SEQ + MT * 12)     // 9 x 128 f32
#define OFF_B1 (OFF_W1 + NSEQ * HID)
#define OFF_B2 (OFF_B1 + HID)
#define OFF_W3 (OFF_B2 + HID)          // 128 x float2
#define OFF_RED (OFF_W3 + HID * 2)     // 128 x 12 f32
#define SMEM_FLOATS (OFF_RED + MT * 12)
#define SMEM_BYTES (SMEM_FLOATS * 4)

typedef unsigned int u32;
typedef unsigned long long u64;

__device__ __forceinline__ float tanh_fast(float x) {
    asm("tanh.approx.f32 %0, %0;" : "+f"(x));
    return x;
}
__device__ __forceinline__ u32 cvt_tf32(float f) {
    u32 r;
    asm("cvt.rna.tf32.f32 %0, %1;" : "=r"(r) : "f"(f));
    return r;
}
__device__ __forceinline__ u64 pk2(float v) {
    u64 r;
    asm("mov.b64 %0, {%1, %1};" : "=l"(r) : "f"(v));
    return r;
}
__device__ __forceinline__ u64 ffma2(u64 a, u64 b, u64 c) {
    u64 d;
    asm("fma.rn.f32x2 %0, %1, %2, %3;" : "=l"(d) : "l"(a), "l"(b), "l"(c));
    return d;
}
__device__ __forceinline__ void unpk(u64 v, float& lo, float& hi) {
    asm("mov.b64 {%0, %1}, %2;" : "=f"(lo), "=f"(hi) : "l"(v));
}
__device__ __forceinline__ void mma_tf32(float* d, const u32* a, const u32* b) {
    asm volatile(
        "mma.sync.aligned.m16n8k8.row.col.f32.tf32.tf32.f32 "
        "{%0,%1,%2,%3}, {%4,%5,%6,%7}, {%8,%9}, {%0,%1,%2,%3};"
        : "+f"(d[0]), "+f"(d[1]), "+f"(d[2]), "+f"(d[3])
        : "r"(a[0]), "r"(a[1]), "r"(a[2]), "r"(a[3]), "r"(b[0]), "r"(b[1]));
}

// ---------------------------------------------------------------------------
// Kernel 1: RK4 scan over T per batch row; writes xG(t) into d_out.
// ---------------------------------------------------------------------------
__global__ void rk4_kernel(const float* __restrict__ inp,
                           const float* __restrict__ x0,
                           float* __restrict__ out) {
    int b = blockIdx.x * blockDim.x + threadIdx.x;
    if (b >= BB) return;
    float2 x = ((const float2*)x0)[b];
    float xa = x.x, xb = x.y;
    const float* up = inp + (size_t)b * TT * NFEAT;
    float2* op = (float2*)out + (size_t)b * TT;
    const float RT = 0.1f, HD2 = 0.05f, H = 0.1f, H6 = 0.1f / 6.0f;
    for (int t0 = 0; t0 < TT; t0 += 8) {
        float u[8];
#pragma unroll
        for (int j = 0; j < 8; j++) u[j] = up[(t0 + j) * NFEAT];
#pragma unroll
        for (int j = 0; j < 8; j++) {
            op[t0 + j] = make_float2(xa, xb);
            float uu = u[j];
            float k1a = (uu - xa) * RT - xa;
            float k1b = xa - xb * RT;
            float x2a = fmaf(HD2, k1a, xa), x2b = fmaf(HD2, k1b, xb);
            float k2a = (uu - x2a) * RT - x2a;
            float k2b = x2a - x2b * RT;
            float x3a = fmaf(HD2, k2a, xa), x3b = fmaf(HD2, k2b, xb);
            float k3a = (uu - x3a) * RT - x3a;
            float k3b = x3a - x3b * RT;
            float x4a = fmaf(H, k3a, xa), x4b = fmaf(H, k3b, xb);
            float k4a = (uu - x4a) * RT - x4a;
            float k4b = x4a - x4b * RT;
            xa = fmaf(H6, k1a + 2.0f * (k2a + k3a) + k4a, xa);
            xb = fmaf(H6, k1b + 2.0f * (k2b + k3b) + k4b, xb);
        }
    }
}

// ---------------------------------------------------------------------------
// Kernel 2: persistent fused MLP. Phase1 (h1) on CUDA cores w/ f32x2; the
// 128x128x128 layer via legacy mma.sync tf32 (single pass); epilogue in regs.
// ---------------------------------------------------------------------------
__global__ __launch_bounds__(THREADS, 1) void nn_kernel(
    const float* __restrict__ inp, const float* __restrict__ gW1,
    const float* __restrict__ gb1, const float* __restrict__ gW2,
    const float* __restrict__ gb2, const float* __restrict__ gW3,
    float* __restrict__ out) {
    extern __shared__ float sm[];
    u32* sATu = (u32*)(sm + OFF_AT);
    u32* sBTu = (u32*)(sm + OFF_BT);
    float* sSeq = sm + OFF_SEQ;
    float* sW1 = sm + OFF_W1;
    float* sB1 = sm + OFF_B1;
    float* sB2 = sm + OFF_B2;
    float* sW3 = sm + OFF_W3;
    float* sRed = sm + OFF_RED;
    const int tid = threadIdx.x;

    // ---- phase 0: weights -> SMEM (once) ----
    for (int i = tid; i < HID * HID; i += THREADS) {
        int k = i >> 7, n = i & 127;
        sBTu[k * LDF + n] = cvt_tf32(gW2[i]);
    }
    for (int i = tid; i < NSEQ * HID; i += THREADS) sW1[i] = gW1[i];
    if (tid < HID) {
        sB1[tid] = gb1[tid];
        sB2[tid] = gb2[tid];
    }
    for (int i = tid; i < HID * 2; i += THREADS) sW3[i] = gW3[i];
    __syncthreads();

    // phase-1 mapping: thread = (m, kgroup)
    const int pm = tid & 127, kg = tid >> 7;
    // phase-2 mapping
    const int w = tid >> 5, lane = tid & 31;
    const int g = lane >> 2, t = lane & 3;
    const int m0 = (w & 3) * 32, n0 = (w >> 2) * 32;

    for (int tile = blockIdx.x; tile < NTILES; tile += GRID) {
        const int tok0 = tile * MT;
        __syncthreads();

        // ---- load seq tile ----
        for (int i = tid; i < MT * NSEQ; i += THREADS) {
            int m = i / NSEQ, j = i - m * NSEQ;
            sSeq[m * 12 + j] = __ldg(&inp[(size_t)(tok0 + m) * NFEAT + 1 + j]);
        }
        __syncthreads();

        // ---- phase 1: h1[k][m] = tf32(tanh(seq[m]·W1[:,k] + b1[k])) ----
        {
            const float* sp = sSeq + pm * 12;
            float4 q0 = *(const float4*)sp;
            float4 q1 = *(const float4*)(sp + 4);
            float q8 = sp[8];
            u64 sv[9] = {pk2(q0.x), pk2(q0.y), pk2(q0.z), pk2(q0.w),
                         pk2(q1.x), pk2(q1.y), pk2(q1.z), pk2(q1.w), pk2(q8)};
            const int kbase = kg * 32;
#pragma unroll 4
            for (int kp = 0; kp < 16; kp++) {
                int k = kbase + 2 * kp;
                u64 acc = *(const u64*)(sB1 + k);
#pragma unroll
                for (int j = 0; j < NSEQ; j++) {
                    u64 wv = *(const u64*)(sW1 + j * HID + k);
                    acc = ffma2(sv[j], wv, acc);
                }
                float lo, hi;
                unpk(acc, lo, hi);
                sATu[k * LDF + pm] = cvt_tf32(tanh_fast(lo));
                sATu[(k + 1) * LDF + pm] = cvt_tf32(tanh_fast(hi));
            }
        }
        __syncthreads();

        // ---- phase 2: 128x128x128 tf32 mma.sync GEMM ----
        float d[2][4][4];
#pragma unroll
        for (int mt = 0; mt < 2; mt++)
#pragma unroll
            for (int nt = 0; nt < 4; nt++)
#pragma unroll
                for (int e = 0; e < 4; e++) d[mt][nt][e] = 0.f;

#pragma unroll 2
        for (int ks = 0; ks < 16; ks++) {
            const int kb = ks * 8;
            const u32* A0 = sATu + (kb + t) * LDF;
            const u32* A4 = sATu + (kb + t + 4) * LDF;
            const u32* B0 = sBTu + (kb + t) * LDF + n0;
            const u32* B4 = sBTu + (kb + t + 4) * LDF + n0;
            u32 a[2][4], b[4][2];
#pragma unroll
            for (int mt = 0; mt < 2; mt++) {
                int rb = m0 + mt * 16 + g;
                a[mt][0] = A0[rb];
                a[mt][1] = A0[rb + 8];
                a[mt][2] = A4[rb];
                a[mt][3] = A4[rb + 8];
            }
#pragma unroll
            for (int nt = 0; nt < 4; nt++) {
                b[nt][0] = B0[nt * 8 + g];
                b[nt][1] = B4[nt * 8 + g];
            }
#pragma unroll
            for (int mt = 0; mt < 2; mt++)
#pragma unroll
                for (int nt = 0; nt < 4; nt++) mma_tf32(d[mt][nt], a[mt], b[nt]);
        }

        // ---- epilogue: h2 = tanh(d + b2); r = h2 @ W3; quad-shuffle reduce ----
        {
            float s0[2][2] = {{0.f, 0.f}, {0.f, 0.f}};
            float s1[2][2] = {{0.f, 0.f}, {0.f, 0.f}};
#pragma unroll
            for (int nt = 0; nt < 4; nt++)
#pragma unroll
                for (int e = 0; e < 2; e++) {
                    int n = n0 + nt * 8 + 2 * t + e;
                    float b2v = sB2[n];
                    float2 w3v = ((const float2*)sW3)[n];
#pragma unroll
                    for (int mt = 0; mt < 2; mt++) {
                        float hA = tanh_fast(d[mt][nt][e] + b2v);      // row g
                        float hB = tanh_fast(d[mt][nt][2 + e] + b2v);  // row g+8
                        s0[mt][0] = fmaf(hA, w3v.x, s0[mt][0]);
                        s1[mt][0] = fmaf(hA, w3v.y, s1[mt][0]);
                        s0[mt][1] = fmaf(hB, w3v.x, s0[mt][1]);
                        s1[mt][1] = fmaf(hB, w3v.y, s1[mt][1]);
                    }
                }
#pragma unroll
            for (int mt = 0; mt < 2; mt++)
#pragma unroll
                for (int h = 0; h < 2; h++) {
                    s0[mt][h] += __shfl_xor_sync(~0u, s0[mt][h], 1);
                    s0[mt][h] += __shfl_xor_sync(~0u, s0[mt][h], 2);
                    s1[mt][h] += __shfl_xor_sync(~0u, s1[mt][h], 1);
                    s1[mt][h] += __shfl_xor_sync(~0u, s1[mt][h], 2);
                }
            if (t == 0) {
                int nb = w >> 2;
#pragma unroll
                for (int mt = 0; mt < 2; mt++)
#pragma unroll
                    for (int h = 0; h < 2; h++) {
                        int r = m0 + mt * 16 + h * 8 + g;
                        sRed[r * 12 + nb] = s0[mt][h];
                        sRed[r * 12 + 4 + nb] = s1[mt][h];
                    }
            }
        }
        __syncthreads();

        // ---- final: sum 4 n-block partials, add xG from d_out ----
        if (tid < 256) {
            int r = tid >> 1, c = tid & 1;
            float4 v = *(const float4*)(sRed + r * 12 + c * 4);
            out[(size_t)(tok0 + r) * 2 + c] += (v.x + v.y) + (v.z + v.w);
        }
    }
}

// ---------------------------------------------------------------------------
extern "C" void kernel_launch(void* const* d_in, const int* in_sizes, int n_in,
                              void* d_out, int out_size) {
    const float* inp = (const float*)d_in[0];
    const float* x0 = (const float*)d_in[1];
    const float* W1 = (const float*)d_in[2];
    const float* b1 = (const float*)d_in[3];
    const float* W2 = (const float*)d_in[4];
    const float* b2 = (const float*)d_in[5];
    const float* W3 = (const float*)d_in[6];
    float* out = (float*)d_out;

    cudaFuncSetAttribute(nn_kernel, cudaFuncAttributeMaxDynamicSharedMemorySize,
                         SMEM_BYTES);

    rk4_kernel<<<BB / 256, 256>>>(inp, x0, out);
    nn_kernel<<<GRID, THREADS, SMEM_BYTES>>>(inp, W1, b1, W2, b2, W3, out);
}

// round 6
// speedup vs baseline: 3.7237x; 1.8936x over previous
#include <cuda_runtime.h>
#include <cuda_fp16.h>
#include <cstdint>

#define BB 2048
#define TT 1024
#define NFEAT 10
#define NSEQ 9
#define HID 128
#define MT 128
#define NTILES ((BB * TT) / MT)
#define THREADS 512
#define GRID 148
#define CH 32           // rk4 chunk length
#define NCH (TT / CH)   // 32 chunks per row

// ---- shared memory layout (u32/float units) ----
#define LDAH 136   // 136 mod 32 == 8 -> conflict-free t-group spread
#define LDBH 136
#define OFF_AH 0                        // h1 half2 [kp=64][m=128]
#define OFF_BH (OFF_AH + 64 * LDAH)     // W2 half2 [kp=64][n=128]
#define OFF_SEQ (OFF_BH + 64 * LDBH)    // 128 x 12 f32
#define OFF_W1 (OFF_SEQ + MT * 12)      // 9 x 128 f32
#define OFF_B1 (OFF_W1 + NSEQ * HID)
#define OFF_B2 (OFF_B1 + HID)
#define OFF_W3 (OFF_B2 + HID)           // 128 x float2
#define OFF_RED (OFF_W3 + HID * 2)      // 128 x 12 f32
#define SMEM_FLOATS (OFF_RED + MT * 12)
#define SMEM_BYTES (SMEM_FLOATS * 4)

typedef unsigned int u32;
typedef unsigned long long u64;

// rk4 scratch (static device globals: allowed)
__device__ float2 g_d[BB * NCH];
__device__ float2 g_xs[BB * NCH];

__device__ __forceinline__ float tanh_fast(float x) {
    asm("tanh.approx.f32 %0, %0;" : "+f"(x));
    return x;
}
__device__ __forceinline__ u64 pk2(float v) {
    u64 r;
    asm("mov.b64 %0, {%1, %1};" : "=l"(r) : "f"(v));
    return r;
}
__device__ __forceinline__ u64 ffma2(u64 a, u64 b, u64 c) {
    u64 d;
    asm("fma.rn.f32x2 %0, %1, %2, %3;" : "=l"(d) : "l"(a), "l"(b), "l"(c));
    return d;
}
__device__ __forceinline__ void unpk(u64 v, float& lo, float& hi) {
    asm("mov.b64 {%0, %1}, %2;" : "=f"(lo), "=f"(hi) : "l"(v));
}
__device__ __forceinline__ u32 pkh2(float lo, float hi) {
    __half2 h = __floats2half2_rn(lo, hi);
    return *reinterpret_cast<u32*>(&h);
}
__device__ __forceinline__ void mma_f16(float* d, const u32* a, const u32* b) {
    asm volatile(
        "mma.sync.aligned.m16n8k16.row.col.f32.f16.f16.f32 "
        "{%0,%1,%2,%3}, {%4,%5,%6,%7}, {%8,%9}, {%0,%1,%2,%3};"
        : "+f"(d[0]), "+f"(d[1]), "+f"(d[2]), "+f"(d[3])
        : "r"(a[0]), "r"(a[1]), "r"(a[2]), "r"(a[3]), "r"(b[0]), "r"(b[1]));
}

// ---------------------------------------------------------------------------
// RK4: one step is an exact affine map x' = M x + N u (the ODE is linear).
// ---------------------------------------------------------------------------
__device__ __forceinline__ float2 rk4_step(float xa, float xb, float uu) {
    const float RT = 0.1f, HD2 = 0.05f, H = 0.1f, H6 = 0.1f / 6.0f;
    float k1a = (uu - xa) * RT - xa;
    float k1b = xa - xb * RT;
    float x2a = fmaf(HD2, k1a, xa), x2b = fmaf(HD2, k1b, xb);
    float k2a = (uu - x2a) * RT - x2a;
    float k2b = x2a - x2b * RT;
    float x3a = fmaf(HD2, k2a, xa), x3b = fmaf(HD2, k2b, xb);
    float k3a = (uu - x3a) * RT - x3a;
    float k3b = x3a - x3b * RT;
    float x4a = fmaf(H, k3a, xa), x4b = fmaf(H, k3b, xb);
    float k4a = (uu - x4a) * RT - x4a;
    float k4b = x4a - x4b * RT;
    return make_float2(fmaf(H6, k1a + 2.0f * (k2a + k3a) + k4a, xa),
                       fmaf(H6, k1b + 2.0f * (k2b + k3b) + k4b, xb));
}
__device__ __forceinline__ void rk4_MN(float& m00, float& m01, float& m10,
                                       float& m11, float& n0, float& n1) {
    float2 e1 = rk4_step(1.f, 0.f, 0.f);
    float2 e2 = rk4_step(0.f, 1.f, 0.f);
    float2 en = rk4_step(0.f, 0.f, 1.f);
    m00 = e1.x; m10 = e1.y; m01 = e2.x; m11 = e2.y; n0 = en.x; n1 = en.y;
}

// r1: per-chunk affine offsets d_c = sum_j M^(31-j) N u_j
__global__ void rk4_r1(const float* __restrict__ inp) {
    int idx = blockIdx.x * blockDim.x + threadIdx.x;
    int b = idx >> 5, c = idx & (NCH - 1);
    float m00, m01, m10, m11, n0, n1;
    rk4_MN(m00, m01, m10, m11, n0, n1);
    const float* up = inp + ((size_t)b * TT + c * CH) * NFEAT;
    float ya = 0.f, yb = 0.f;
#pragma unroll 8
    for (int j = 0; j < CH; j++) {
        float u = up[j * NFEAT];
        float ta = fmaf(m00, ya, fmaf(m01, yb, n0 * u));
        float tb = fmaf(m10, ya, fmaf(m11, yb, n1 * u));
        ya = ta; yb = tb;
    }
    g_d[idx] = make_float2(ya, yb);
}

// r2: scan chunk boundaries with M^32
__global__ void rk4_r2(const float* __restrict__ x0) {
    int b = blockIdx.x * blockDim.x + threadIdx.x;
    if (b >= BB) return;
    float m00, m01, m10, m11, n0, n1;
    rk4_MN(m00, m01, m10, m11, n0, n1);
    // M^32 by 5 squarings
    float a00 = m00, a01 = m01, a10 = m10, a11 = m11;
#pragma unroll
    for (int s = 0; s < 5; s++) {
        float t00 = a00 * a00 + a01 * a10;
        float t01 = a00 * a01 + a01 * a11;
        float t10 = a10 * a00 + a11 * a10;
        float t11 = a10 * a01 + a11 * a11;
        a00 = t00; a01 = t01; a10 = t10; a11 = t11;
    }
    float xa = x0[2 * b], xb = x0[2 * b + 1];
#pragma unroll 4
    for (int c = 0; c < NCH; c++) {
        g_xs[b * NCH + c] = make_float2(xa, xb);
        float2 d = g_d[b * NCH + c];
        float ta = fmaf(a00, xa, fmaf(a01, xb, d.x));
        float tb = fmaf(a10, xa, fmaf(a11, xb, d.y));
        xa = ta; xb = tb;
    }
}

// r3: replay chunks in parallel, writing xG(t) (pre-update state) to out
__global__ void rk4_r3(const float* __restrict__ inp, float* __restrict__ out) {
    int idx = blockIdx.x * blockDim.x + threadIdx.x;
    int b = idx >> 5, c = idx & (NCH - 1);
    float m00, m01, m10, m11, n0, n1;
    rk4_MN(m00, m01, m10, m11, n0, n1);
    const float* up = inp + ((size_t)b * TT + c * CH) * NFEAT;
    float2* op = (float2*)out + (size_t)b * TT + c * CH;
    float2 x = g_xs[idx];
    float xa = x.x, xb = x.y;
#pragma unroll 8
    for (int j = 0; j < CH; j++) {
        op[j] = make_float2(xa, xb);
        float u = up[j * NFEAT];
        float ta = fmaf(m00, xa, fmaf(m01, xb, n0 * u));
        float tb = fmaf(m10, xa, fmaf(m11, xb, n1 * u));
        xa = ta; xb = tb;
    }
}

// ---------------------------------------------------------------------------
// Persistent fused MLP. Phase1 on CUDA cores (f32x2), h1 packed to half2.
// 128x128x128 layer via mma.sync m16n8k16 fp16 (11-bit mantissa == tf32).
// ---------------------------------------------------------------------------
__global__ __launch_bounds__(THREADS, 1) void nn_kernel(
    const float* __restrict__ inp, const float* __restrict__ gW1,
    const float* __restrict__ gb1, const float* __restrict__ gW2,
    const float* __restrict__ gb2, const float* __restrict__ gW3,
    float* __restrict__ out) {
    extern __shared__ float sm[];
    u32* sAh = (u32*)(sm + OFF_AH);
    u32* sBh = (u32*)(sm + OFF_BH);
    float* sSeq = sm + OFF_SEQ;
    float* sW1 = sm + OFF_W1;
    float* sB1 = sm + OFF_B1;
    float* sB2 = sm + OFF_B2;
    float* sW3 = sm + OFF_W3;
    float* sRed = sm + OFF_RED;
    const int tid = threadIdx.x;

    // ---- phase 0: weights -> SMEM (once) ----
    // W2 packed as half2 k-pairs: Bh[kp][n] = (W2[2kp][n], W2[2kp+1][n])
    for (int i = tid; i < 64 * HID; i += THREADS) {
        int kp = i >> 7, n = i & 127;
        sBh[kp * LDBH + n] = pkh2(gW2[(2 * kp) * HID + n], gW2[(2 * kp + 1) * HID + n]);
    }
    for (int i = tid; i < NSEQ * HID; i += THREADS) sW1[i] = gW1[i];
    if (tid < HID) {
        sB1[tid] = gb1[tid];
        sB2[tid] = gb2[tid];
    }
    for (int i = tid; i < HID * 2; i += THREADS) sW3[i] = gW3[i];
    __syncthreads();

    const int pm = tid & 127, kg = tid >> 7;       // phase-1 map
    const int w = tid >> 5, lane = tid & 31;       // phase-2 map
    const int g = lane >> 2, t = lane & 3;
    const int m0 = (w & 3) * 32, n0 = (w >> 2) * 32;

    for (int tile = blockIdx.x; tile < NTILES; tile += GRID) {
        const int tok0 = tile * MT;
        __syncthreads();

        // ---- load seq tile ----
        for (int i = tid; i < MT * NSEQ; i += THREADS) {
            int m = i / NSEQ, j = i - m * NSEQ;
            sSeq[m * 12 + j] = __ldg(&inp[(size_t)(tok0 + m) * NFEAT + 1 + j]);
        }
        __syncthreads();

        // ---- phase 1: h1 = tanh(seq@W1+b1), packed half2 k-pairs ----
        {
            const float* sp = sSeq + pm * 12;
            float4 q0 = *(const float4*)sp;
            float4 q1 = *(const float4*)(sp + 4);
            float q8 = sp[8];
            u64 sv[9] = {pk2(q0.x), pk2(q0.y), pk2(q0.z), pk2(q0.w),
                         pk2(q1.x), pk2(q1.y), pk2(q1.z), pk2(q1.w), pk2(q8)};
            const int kbase = kg * 32;
#pragma unroll 4
            for (int kpi = 0; kpi < 16; kpi++) {
                int k = kbase + 2 * kpi;
                u64 acc = *(const u64*)(sB1 + k);
#pragma unroll
                for (int j = 0; j < NSEQ; j++) {
                    u64 wv = *(const u64*)(sW1 + j * HID + k);
                    acc = ffma2(sv[j], wv, acc);
                }
                float lo, hi;
                unpk(acc, lo, hi);
                sAh[(kg * 16 + kpi) * LDAH + pm] = pkh2(tanh_fast(lo), tanh_fast(hi));
            }
        }
        __syncthreads();

        // ---- phase 2: fp16 m16n8k16 GEMM with next-k prefetch ----
        float d[2][4][4];
#pragma unroll
        for (int mt = 0; mt < 2; mt++)
#pragma unroll
            for (int nt = 0; nt < 4; nt++)
#pragma unroll
                for (int e = 0; e < 4; e++) d[mt][nt][e] = 0.f;

        u32 ac[8], bc[8];
        {
            const u32* A0 = sAh + t * LDAH;
            const u32* A4 = A0 + 4 * LDAH;
            const u32* B0 = sBh + t * LDBH;
            const u32* B4 = B0 + 4 * LDBH;
#pragma unroll
            for (int mt = 0; mt < 2; mt++) {
                int r = m0 + mt * 16 + g;
                ac[mt * 4 + 0] = A0[r];
                ac[mt * 4 + 1] = A0[r + 8];
                ac[mt * 4 + 2] = A4[r];
                ac[mt * 4 + 3] = A4[r + 8];
            }
#pragma unroll
            for (int nt = 0; nt < 4; nt++) {
                int n = n0 + nt * 8 + g;
                bc[nt * 2 + 0] = B0[n];
                bc[nt * 2 + 1] = B4[n];
            }
        }
#pragma unroll
        for (int ks = 0; ks < 8; ks++) {
            u32 an[8], bn[8];
            if (ks < 7) {
                const u32* A0 = sAh + (8 * (ks + 1) + t) * LDAH;
                const u32* A4 = A0 + 4 * LDAH;
                const u32* B0 = sBh + (8 * (ks + 1) + t) * LDBH;
                const u32* B4 = B0 + 4 * LDBH;
#pragma unroll
                for (int mt = 0; mt < 2; mt++) {
                    int r = m0 + mt * 16 + g;
                    an[mt * 4 + 0] = A0[r];
                    an[mt * 4 + 1] = A0[r + 8];
                    an[mt * 4 + 2] = A4[r];
                    an[mt * 4 + 3] = A4[r + 8];
                }
#pragma unroll
                for (int nt = 0; nt < 4; nt++) {
                    int n = n0 + nt * 8 + g;
                    bn[nt * 2 + 0] = B0[n];
                    bn[nt * 2 + 1] = B4[n];
                }
            }
#pragma unroll
            for (int mt = 0; mt < 2; mt++)
#pragma unroll
                for (int nt = 0; nt < 4; nt++)
                    mma_f16(d[mt][nt], ac + mt * 4, bc + nt * 2);
            if (ks < 7) {
#pragma unroll
                for (int i = 0; i < 8; i++) {
                    ac[i] = an[i];
                    bc[i] = bn[i];
                }
            }
        }

        // ---- epilogue: h2 = tanh(d+b2); r = h2@W3; quad-shuffle reduce ----
        {
            float s0[2][2] = {{0.f, 0.f}, {0.f, 0.f}};
            float s1[2][2] = {{0.f, 0.f}, {0.f, 0.f}};
#pragma unroll
            for (int nt = 0; nt < 4; nt++)
#pragma unroll
                for (int e = 0; e < 2; e++) {
                    int n = n0 + nt * 8 + 2 * t + e;
                    float b2v = sB2[n];
                    float2 w3v = ((const float2*)sW3)[n];
#pragma unroll
                    for (int mt = 0; mt < 2; mt++) {
                        float hA = tanh_fast(d[mt][nt][e] + b2v);
                        float hB = tanh_fast(d[mt][nt][2 + e] + b2v);
                        s0[mt][0] = fmaf(hA, w3v.x, s0[mt][0]);
                        s1[mt][0] = fmaf(hA, w3v.y, s1[mt][0]);
                        s0[mt][1] = fmaf(hB, w3v.x, s0[mt][1]);
                        s1[mt][1] = fmaf(hB, w3v.y, s1[mt][1]);
                    }
                }
#pragma unroll
            for (int mt = 0; mt < 2; mt++)
#pragma unroll
                for (int h = 0; h < 2; h++) {
                    s0[mt][h] += __shfl_xor_sync(~0u, s0[mt][h], 1);
                    s0[mt][h] += __shfl_xor_sync(~0u, s0[mt][h], 2);
                    s1[mt][h] += __shfl_xor_sync(~0u, s1[mt][h], 1);
                    s1[mt][h] += __shfl_xor_sync(~0u, s1[mt][h], 2);
                }
            if (t == 0) {
                int nb = w >> 2;
#pragma unroll
                for (int mt = 0; mt < 2; mt++)
#pragma unroll
                    for (int h = 0; h < 2; h++) {
                        int r = m0 + mt * 16 + h * 8 + g;
                        sRed[r * 12 + nb] = s0[mt][h];
                        sRed[r * 12 + 4 + nb] = s1[mt][h];
                    }
            }
        }
        __syncthreads();

        // ---- final: sum 4 n-block partials, add xG from d_out ----
        if (tid < 256) {
            int r = tid >> 1, c = tid & 1;
            float4 v = *(const float4*)(sRed + r * 12 + c * 4);
            out[(size_t)(tok0 + r) * 2 + c] += (v.x + v.y) + (v.z + v.w);
        }
    }
}

// ---------------------------------------------------------------------------
extern "C" void kernel_launch(void* const* d_in, const int* in_sizes, int n_in,
                              void* d_out, int out_size) {
    const float* inp = (const float*)d_in[0];
    const float* x0 = (const float*)d_in[1];
    const float* W1 = (const float*)d_in[2];
    const float* b1 = (const float*)d_in[3];
    const float* W2 = (const float*)d_in[4];
    const float* b2 = (const float*)d_in[5];
    const float* W3 = (const float*)d_in[6];
    float* out = (float*)d_out;

    cudaFuncSetAttribute(nn_kernel, cudaFuncAttributeMaxDynamicSharedMemorySize,
                         SMEM_BYTES);

    rk4_r1<<<(BB * NCH) / 256, 256>>>(inp);
    rk4_r2<<<BB / 256, 256>>>(x0);
    rk4_r3<<<(BB * NCH) / 256, 256>>>(inp, out);
    nn_kernel<<<GRID, THREADS, SMEM_BYTES>>>(inp, W1, b1, W2, b2, W3, out);
}